// round 13
// baseline (speedup 1.0000x reference)
#include <cuda_runtime.h>
#include <cuda_bf16.h>

#define N_NODES 100000
#define N_EDGES 1600000
#define E_TOT   (N_EDGES + N_NODES)
#define N_GRAPHS 64
#define NEG_SLOPE 0.2f
#define SCAN_BLK 1024
#define N_SBLK   ((N_NODES + SCAN_BLK - 1) / SCAN_BLK)   // 98
#define N_TILES  (N_NODES / 16)                          // 6250
#define TPB      8                                       // gemm2 tiles per block

// ---------------- scratch (device globals; no allocation) ----------------
__device__ float    g_s1[8], g_d1[8];
__device__ int      g_ei_is64, g_b_is64;
__device__ int      g_batch[N_NODES];
__device__ int      g_deg[N_NODES];
__device__ int      g_incl[N_NODES];
__device__ int      g_bsum[N_SBLK];
__device__ int      g_rowstart[N_NODES + 1];
__device__ int      g_cursor[N_NODES];
__device__ int      g_csr_src[E_TOT];
__device__ float    g_t1  [N_NODES * 8];
__device__ __nv_bfloat162 g_h2b[N_NODES * 64];   // h2 in bf16 (message values)
__device__ float    g_as2 [N_NODES * 8];
__device__ float    g_ad2 [N_NODES * 8];
__device__ float    g_pool[N_NODES * 16];        // per-node pooled head-mean

__device__ __forceinline__ float lrelu(float v) {
    return v > 0.f ? v : NEG_SLOPE * v;
}

// packed f32x2 helpers
__device__ __forceinline__ unsigned long long pack2(float lo, float hi) {
    unsigned long long r;
    asm("mov.b64 %0, {%1, %2};" : "=l"(r) : "f"(lo), "f"(hi));
    return r;
}
__device__ __forceinline__ void unpack2(unsigned long long p, float& lo, float& hi) {
    asm("mov.b64 {%0, %1}, %2;" : "=f"(lo), "=f"(hi) : "l"(p));
}
__device__ __forceinline__ void ffma2(unsigned long long& acc,
                                      unsigned long long a,
                                      unsigned long long b) {
    asm("fma.rn.f32x2 %0, %1, %2, %0;" : "+l"(acc) : "l"(a), "l"(b));
}

// accumulate 8 bf16 channels (one uint4) with weight w
__device__ __forceinline__ void acc8(const uint4 v, float w, float* a) {
    float2 f;
    f = __bfloat1622float2(*reinterpret_cast<const __nv_bfloat162*>(&v.x));
    a[0] = fmaf(w, f.x, a[0]); a[1] = fmaf(w, f.y, a[1]);
    f = __bfloat1622float2(*reinterpret_cast<const __nv_bfloat162*>(&v.y));
    a[2] = fmaf(w, f.x, a[2]); a[3] = fmaf(w, f.y, a[3]);
    f = __bfloat1622float2(*reinterpret_cast<const __nv_bfloat162*>(&v.z));
    a[4] = fmaf(w, f.x, a[4]); a[5] = fmaf(w, f.y, a[5]);
    f = __bfloat1622float2(*reinterpret_cast<const __nv_bfloat162*>(&v.w));
    a[6] = fmaf(w, f.x, a[6]); a[7] = fmaf(w, f.y, a[7]);
}

// low-word index fetch: for int64 buffers (values >=0 < 2^31, little-endian)
__device__ __forceinline__ int idx_at(const int* p, int i, int is64) {
    return is64 ? p[i << 1] : p[i];
}

// ---------------- setup ----------------

__global__ void k_misc(const int* __restrict__ ei,
                       const int* __restrict__ ba,
                       const float* __restrict__ W1,
                       const float* __restrict__ att_src1,
                       const float* __restrict__ att_dst1) {
    int i = blockIdx.x * blockDim.x + threadIdx.x;
    if (i < N_NODES) g_deg[i] = 0;
    if (blockIdx.x == 0) {
        __shared__ int s_e, s_b;
        int t = threadIdx.x;
        if (t == 0) { s_e = 1; s_b = 1; }
        __syncthreads();
        if (t < 64) {
            int we = 2 * (t * 24999 + 13) + 1;      // < 3,200,000
            if (ei[we] != 0) atomicExch(&s_e, 0);
            int wb = (N_NODES - 1) - 2 * t;         // odd, in-bounds
            if (ba[wb] != 0) atomicExch(&s_b, 0);
        }
        __syncthreads();
        if (t == 0) {
            g_ei_is64 = s_e;
            g_b_is64  = s_b;
            g_rowstart[N_NODES] = E_TOT;
        }
        if (t < 8) {
            float a = 0.f, b = 0.f;
            for (int c = 0; c < 8; c++) {
                a += W1[t * 8 + c] * att_src1[t * 8 + c];
                b += W1[t * 8 + c] * att_dst1[t * 8 + c];
            }
            g_s1[t] = a;
            g_d1[t] = b;
        }
    }
}

__global__ void k_hist(const int* __restrict__ eiv,
                       const int* __restrict__ bav) {
    int i = blockIdx.x * blockDim.x + threadIdx.x;
    int is64 = g_ei_is64;
    if (i < E_TOT) {
        int d = (i < N_EDGES) ? idx_at(eiv, N_EDGES + i, is64)
                              : i - N_EDGES;
        atomicAdd(&g_deg[d], 1);
    }
    if (i < N_NODES)
        g_batch[i] = idx_at(bav, i, g_b_is64);
}

__global__ void k_scan1() {
    __shared__ int sh[SCAN_BLK];
    int t = threadIdx.x;
    int i = blockIdx.x * SCAN_BLK + t;
    int v = (i < N_NODES) ? g_deg[i] : 0;
    sh[t] = v;
    __syncthreads();
#pragma unroll
    for (int off = 1; off < SCAN_BLK; off <<= 1) {
        int tmp = (t >= off) ? sh[t - off] : 0;
        __syncthreads();
        sh[t] += tmp;
        __syncthreads();
    }
    if (i < N_NODES) g_incl[i] = sh[t];
    if (t == SCAN_BLK - 1) g_bsum[blockIdx.x] = sh[t];
}

__global__ void k_scan3() {
    __shared__ int s_boff;
    if (threadIdx.x < 32) {
        int sb = blockIdx.x >> 2;    // scan1 block index (1024/256)
        int acc = 0;
        for (int j = threadIdx.x; j < sb; j += 32) acc += g_bsum[j];
#pragma unroll
        for (int off = 16; off >= 1; off >>= 1)
            acc += __shfl_xor_sync(0xffffffffu, acc, off);
        if (threadIdx.x == 0) s_boff = acc;
    }
    __syncthreads();
    int i = blockIdx.x * blockDim.x + threadIdx.x;
    if (i >= N_NODES) return;
    int rs = g_incl[i] - g_deg[i] + s_boff;
    g_rowstart[i] = rs;
    g_cursor[i]   = rs;
}

__global__ void k_scatter(const int* __restrict__ eiv) {
    int i = blockIdx.x * blockDim.x + threadIdx.x;
    if (i >= E_TOT) return;
    int s, d;
    if (i < N_EDGES) {
        int is64 = g_ei_is64;
        s = idx_at(eiv, i, is64);
        d = idx_at(eiv, N_EDGES + i, is64);
    } else {
        s = i - N_EDGES;
        d = s;
    }
    int p = atomicAdd(&g_cursor[d], 1);
    g_csr_src[p] = s;
}

// ---- layer 1: warp per dst node; direct single pass, no smem ----
__global__ void __launch_bounds__(256) k_l1(const float* __restrict__ x) {
    int w = (blockIdx.x * blockDim.x + threadIdx.x) >> 5;
    if (w >= N_NODES) return;
    int lane = threadIdx.x & 31;
    int eo = lane >> 3, h = lane & 7;
    int start = g_rowstart[w], end = g_rowstart[w + 1];
    float cs = g_s1[h];
    float cd = g_d1[h] * x[w];

    float den = 0.f, num = 0.f;
    for (int j = start + eo; j < end; j += 4) {
        float xs = x[__ldg(&g_csr_src[j])];
        float wj = __expf(fminf(lrelu(fmaf(xs, cs, cd)), 60.f));
        den += wj;
        num += wj * xs;
    }
#pragma unroll
    for (int off = 8; off <= 16; off <<= 1) {
        den += __shfl_xor_sync(0xffffffffu, den, off);
        num += __shfl_xor_sync(0xffffffffu, num, off);
    }
    if (lane < 8) g_t1[w * 8 + h] = num / den;
}

// ---- GEMM2 (8 tiles/block to amortize W2 L2->L1 refill) + elu in + att2 out ----
__global__ void __launch_bounds__(128) k_gemm2(const float* __restrict__ W1,
                                               const float* __restrict__ b1,
                                               const float* __restrict__ W2,
                                               const float* __restrict__ att_src2,
                                               const float* __restrict__ att_dst2) {
    __shared__ float s_in[16][64];
    int t = threadIdx.x;
    int lane = t & 31;
    int ng = t >> 5;
    int c = lane * 4;
    int h = lane >> 2;
    const float* w2p = &W2[c];
    float4 av = *reinterpret_cast<const float4*>(&att_src2[c]);
    float4 dv = *reinterpret_cast<const float4*>(&att_dst2[c]);

    int tile_end = min((int)(blockIdx.x * TPB + TPB), N_TILES);
    for (int tile = blockIdx.x * TPB; tile < tile_end; tile++) {
        int n0 = tile * 16;
        __syncthreads();   // protect s_in reuse across iterations
        for (int e = t; e < 1024; e += 128) {
            int nn = e >> 6, j = e & 63;
            float v = fmaf(g_t1[(n0 + nn) * 8 + (j >> 3)], W1[j], b1[j]);
            s_in[nn][j] = v > 0.f ? v : (__expf(v) - 1.f);
        }
        __syncthreads();

        unsigned long long acc01[4], acc23[4];
#pragma unroll
        for (int i = 0; i < 4; i++) { acc01[i] = 0ull; acc23[i] = 0ull; }
#pragma unroll 4
        for (int k = 0; k < 64; k++) {
            float4 wv = *reinterpret_cast<const float4*>(w2p + k * 128);
            unsigned long long s01 = pack2(s_in[ng * 4 + 0][k], s_in[ng * 4 + 1][k]);
            unsigned long long s23 = pack2(s_in[ng * 4 + 2][k], s_in[ng * 4 + 3][k]);
            unsigned long long w0 = pack2(wv.x, wv.x);
            unsigned long long w1 = pack2(wv.y, wv.y);
            unsigned long long w2 = pack2(wv.z, wv.z);
            unsigned long long w3 = pack2(wv.w, wv.w);
            ffma2(acc01[0], w0, s01); ffma2(acc23[0], w0, s23);
            ffma2(acc01[1], w1, s01); ffma2(acc23[1], w1, s23);
            ffma2(acc01[2], w2, s01); ffma2(acc23[2], w2, s23);
            ffma2(acc01[3], w3, s01); ffma2(acc23[3], w3, s23);
        }
        float4 row[4];
        {
            float lo[4], hi[4];
#pragma unroll
            for (int i = 0; i < 4; i++) unpack2(acc01[i], lo[i], hi[i]);
            row[0] = make_float4(lo[0], lo[1], lo[2], lo[3]);
            row[1] = make_float4(hi[0], hi[1], hi[2], hi[3]);
#pragma unroll
            for (int i = 0; i < 4; i++) unpack2(acc23[i], lo[i], hi[i]);
            row[2] = make_float4(lo[0], lo[1], lo[2], lo[3]);
            row[3] = make_float4(hi[0], hi[1], hi[2], hi[3]);
        }
        int nb = n0 + ng * 4;
#pragma unroll
        for (int r = 0; r < 4; r++) {
            __nv_bfloat162 b0 = __float22bfloat162_rn(make_float2(row[r].x, row[r].y));
            __nv_bfloat162 b1v = __float22bfloat162_rn(make_float2(row[r].z, row[r].w));
            uint2 packed;
            packed.x = *reinterpret_cast<unsigned*>(&b0);
            packed.y = *reinterpret_cast<unsigned*>(&b1v);
            *reinterpret_cast<uint2*>(&g_h2b[(nb + r) * 64 + lane * 2]) = packed;
            float pa = row[r].x * av.x + row[r].y * av.y + row[r].z * av.z + row[r].w * av.w;
            float pd = row[r].x * dv.x + row[r].y * dv.y + row[r].z * dv.z + row[r].w * dv.w;
            pa += __shfl_xor_sync(0xffffffffu, pa, 1);
            pd += __shfl_xor_sync(0xffffffffu, pd, 1);
            pa += __shfl_xor_sync(0xffffffffu, pa, 2);
            pd += __shfl_xor_sync(0xffffffffu, pd, 2);
            if ((lane & 3) == 0) {
                g_as2[(nb + r) * 8 + h] = pa;
                g_ad2[(nb + r) * 8 + h] = pd;
            }
        }
    }
}

// ---- layer 2: SINGLE PASS, zero smem; warp = 1 dst node ----
__global__ void __launch_bounds__(256) k_l2() {
    int d = (blockIdx.x * blockDim.x + threadIdx.x) >> 5;
    if (d >= N_NODES) return;
    int lane = threadIdx.x & 31;
    int start = g_rowstart[d];
    int deg = g_rowstart[d + 1] - start;
    int sub = lane >> 4;       // which edge of the pair
    int q   = lane & 15;       // channel chunk: channels q*8 .. q*8+7
    int h4  = q >> 1;          // head owning this chunk
    float ad4 = g_ad2[d * 8 + h4];
    const int* srcp = &g_csr_src[start];

    float acc[8];
#pragma unroll
    for (int r = 0; r < 8; r++) acc[r] = 0.f;
    float wsum = 0.f;

    int k = 0;
    for (; k + 4 <= deg; k += 4) {
        int s0 = __ldg(&srcp[k + sub]);
        int s1 = __ldg(&srcp[k + 2 + sub]);
        float e0 = lrelu(g_as2[s0 * 8 + h4] + ad4);
        float e1 = lrelu(g_as2[s1 * 8 + h4] + ad4);
        uint4 v0 = *reinterpret_cast<const uint4*>(&g_h2b[s0 * 64 + q * 4]);
        uint4 v1 = *reinterpret_cast<const uint4*>(&g_h2b[s1 * 64 + q * 4]);
        float w0 = __expf(fminf(e0, 60.f));
        float w1 = __expf(fminf(e1, 60.f));
        wsum += w0 + w1;
        acc8(v0, w0, acc);
        acc8(v1, w1, acc);
    }
    for (; k < deg; k += 2) {
        int idx = k + sub;
        bool valid = idx < deg;
        int s0 = __ldg(&srcp[valid ? idx : 0]);
        float w0 = valid
            ? __expf(fminf(lrelu(g_as2[s0 * 8 + h4] + ad4), 60.f)) : 0.f;
        uint4 v0 = *reinterpret_cast<const uint4*>(&g_h2b[s0 * 64 + q * 4]);
        wsum += w0;
        acc8(v0, w0, acc);
    }

    wsum += __shfl_xor_sync(0xffffffffu, wsum, 16);
#pragma unroll
    for (int r = 0; r < 8; r++)
        acc[r] += __shfl_xor_sync(0xffffffffu, acc[r], 16);
    float inv = 0.125f / wsum;
#pragma unroll
    for (int r = 0; r < 8; r++) acc[r] *= inv;
#pragma unroll
    for (int off = 2; off <= 8; off <<= 1) {
#pragma unroll
        for (int r = 0; r < 8; r++)
            acc[r] += __shfl_xor_sync(0xffffffffu, acc[r], off);
    }
    if (lane < 2) {
        float4* dst = reinterpret_cast<float4*>(&g_pool[d * 16 + lane * 8]);
        dst[0] = make_float4(acc[0], acc[1], acc[2], acc[3]);
        dst[1] = make_float4(acc[4], acc[5], acc[6], acc[7]);
    }
}

// one block per graph: sum contiguous node range of g_pool, then FC
__global__ void __launch_bounds__(256) k_final(const float* __restrict__ b2,
                                               const float* __restrict__ Wfc,
                                               const float* __restrict__ bfc,
                                               float* __restrict__ out) {
    __shared__ float s_part[8][16];
    __shared__ float s_pool[16];
    int g = blockIdx.x;
    int t = threadIdx.x;
    int lo = 0, hi = N_NODES;
    while (lo < hi) {
        int mid = (lo + hi) >> 1;
        if (g_batch[mid] < g) lo = mid + 1; else hi = mid;
    }
    int lb = lo;
    lo = 0; hi = N_NODES;
    while (lo < hi) {
        int mid = (lo + hi) >> 1;
        if (g_batch[mid] < g + 1) lo = mid + 1; else hi = mid;
    }
    int ub = lo;
    int c = t & 15;
    float acc = 0.f;
    for (int n = lb + (t >> 4); n < ub; n += 16)
        acc += g_pool[n * 16 + c];
    acc += __shfl_xor_sync(0xffffffffu, acc, 16);
    int wid = t >> 5, lane = t & 31;
    if (lane < 16) s_part[wid][lane] = acc;
    __syncthreads();
    if (t < 16) {
        float v = 0.f;
#pragma unroll
        for (int wds = 0; wds < 8; wds++) v += s_part[wds][t];
        float cnt = (float)(ub - lb);
        s_pool[t] = v / fmaxf(cnt, 1.f) + b2[t];
    }
    __syncthreads();
    if (t < 4) {
        float r = bfc[t];
#pragma unroll
        for (int cc = 0; cc < 16; cc++) r += s_pool[cc] * Wfc[cc * 4 + t];
        out[g * 4 + t] = r;
    }
}

// ---------------- launch ----------------
extern "C" void kernel_launch(void* const* d_in, const int* in_sizes, int n_in,
                              void* d_out, int out_size) {
    const float* x        = (const float*)d_in[0];
    const float* W1       = (const float*)d_in[1];
    const float* att_src1 = (const float*)d_in[2];
    const float* att_dst1 = (const float*)d_in[3];
    const float* b1       = (const float*)d_in[4];
    const float* W2       = (const float*)d_in[5];
    const float* att_src2 = (const float*)d_in[6];
    const float* att_dst2 = (const float*)d_in[7];
    const float* b2       = (const float*)d_in[8];
    const float* Wfc      = (const float*)d_in[9];
    const float* bfc      = (const float*)d_in[10];
    const int*   ei       = (const int*)d_in[11];
    const int*   batch    = (const int*)d_in[12];
    float* out = (float*)d_out;

    const int T = 256;
    int nb_nodes = (N_NODES + T - 1) / T;     // 391
    k_misc<<<nb_nodes, T>>>(ei, batch, W1, att_src1, att_dst1);
    k_hist<<<(E_TOT + T - 1) / T, T>>>(ei, batch);
    k_scan1<<<N_SBLK, SCAN_BLK>>>();
    k_scan3<<<nb_nodes, T>>>();
    k_scatter<<<(E_TOT + T - 1) / T, T>>>(ei);

    k_l1<<<(N_NODES * 32 + T - 1) / T, T>>>(x);
    k_gemm2<<<(N_TILES + TPB - 1) / TPB, 128>>>(W1, b1, W2, att_src2, att_dst2);
    k_l2<<<(N_NODES * 32 + T - 1) / T, T>>>();
    k_final<<<N_GRAPHS, 256>>>(b2, Wfc, bfc, out);
}

// round 14
// speedup vs baseline: 1.1028x; 1.1028x over previous
#include <cuda_runtime.h>
#include <cuda_bf16.h>

#define N_NODES 100000
#define N_EDGES 1600000
#define E_TOT   (N_EDGES + N_NODES)
#define N_GRAPHS 64
#define NEG_SLOPE 0.2f
#define SCAN_BLK 1024
#define N_SBLK   ((N_NODES + SCAN_BLK - 1) / SCAN_BLK)   // 98

// ---------------- scratch (device globals; no allocation) ----------------
// NOTE: g_deg is zero-initialized at module load and re-zeroed at the END of
// every launch (in k_final), so k_hist can histogram immediately.
__device__ float    g_s1[8], g_d1[8];
__device__ int      g_ei_is64, g_b_is64;
__device__ int      g_batch[N_NODES];
__device__ int      g_deg[N_NODES];
__device__ int      g_incl[N_NODES];
__device__ int      g_bsum[N_SBLK];
__device__ int      g_rowstart[N_NODES + 1];
__device__ int      g_cursor[N_NODES];
__device__ int      g_csr_src[E_TOT];
__device__ float    g_t1  [N_NODES * 8];
__device__ __nv_bfloat162 g_h2b[N_NODES * 64];   // h2 in bf16 (message values)
__device__ float    g_as2 [N_NODES * 8];
__device__ float    g_ad2 [N_NODES * 8];
__device__ float    g_pool[N_NODES * 16];        // per-node pooled head-mean

__device__ __forceinline__ float lrelu(float v) {
    return v > 0.f ? v : NEG_SLOPE * v;
}

// packed f32x2 helpers
__device__ __forceinline__ unsigned long long pack2(float lo, float hi) {
    unsigned long long r;
    asm("mov.b64 %0, {%1, %2};" : "=l"(r) : "f"(lo), "f"(hi));
    return r;
}
__device__ __forceinline__ void unpack2(unsigned long long p, float& lo, float& hi) {
    asm("mov.b64 {%0, %1}, %2;" : "=f"(lo), "=f"(hi) : "l"(p));
}
__device__ __forceinline__ void ffma2(unsigned long long& acc,
                                      unsigned long long a,
                                      unsigned long long b) {
    asm("fma.rn.f32x2 %0, %1, %2, %0;" : "+l"(acc) : "l"(a), "l"(b));
}

// accumulate 8 bf16 channels (one uint4) with weight w
__device__ __forceinline__ void acc8(const uint4 v, float w, float* a) {
    float2 f;
    f = __bfloat1622float2(*reinterpret_cast<const __nv_bfloat162*>(&v.x));
    a[0] = fmaf(w, f.x, a[0]); a[1] = fmaf(w, f.y, a[1]);
    f = __bfloat1622float2(*reinterpret_cast<const __nv_bfloat162*>(&v.y));
    a[2] = fmaf(w, f.x, a[2]); a[3] = fmaf(w, f.y, a[3]);
    f = __bfloat1622float2(*reinterpret_cast<const __nv_bfloat162*>(&v.z));
    a[4] = fmaf(w, f.x, a[4]); a[5] = fmaf(w, f.y, a[5]);
    f = __bfloat1622float2(*reinterpret_cast<const __nv_bfloat162*>(&v.w));
    a[6] = fmaf(w, f.x, a[6]); a[7] = fmaf(w, f.y, a[7]);
}

// low-word index fetch: for int64 buffers (values >=0 < 2^31, little-endian)
__device__ __forceinline__ int idx_at(const int* p, int i, int is64) {
    return is64 ? p[i << 1] : p[i];
}

// ---------------- setup ----------------

// single small block: dtype detection + s1/d1 prep + rowstart[N]
__global__ void k_misc(const int* __restrict__ ei,
                       const int* __restrict__ ba,
                       const float* __restrict__ W1,
                       const float* __restrict__ att_src1,
                       const float* __restrict__ att_dst1) {
    __shared__ int s_e, s_b;
    int t = threadIdx.x;  // 64 threads
    if (t == 0) { s_e = 1; s_b = 1; }
    __syncthreads();
    int we = 2 * (t * 24999 + 13) + 1;      // < 3,200,000
    if (ei[we] != 0) atomicExch(&s_e, 0);
    int wb = (N_NODES - 1) - 2 * t;         // odd, in-bounds
    if (ba[wb] != 0) atomicExch(&s_b, 0);
    __syncthreads();
    if (t == 0) {
        g_ei_is64 = s_e;
        g_b_is64  = s_b;
        g_rowstart[N_NODES] = E_TOT;
    }
    if (t < 8) {
        float a = 0.f, b = 0.f;
        for (int c = 0; c < 8; c++) {
            a += W1[t * 8 + c] * att_src1[t * 8 + c];
            b += W1[t * 8 + c] * att_dst1[t * 8 + c];
        }
        g_s1[t] = a;
        g_d1[t] = b;
    }
}

__global__ void k_hist(const int* __restrict__ eiv,
                       const int* __restrict__ bav) {
    int i = blockIdx.x * blockDim.x + threadIdx.x;
    int is64 = g_ei_is64;
    if (i < E_TOT) {
        int d = (i < N_EDGES) ? idx_at(eiv, N_EDGES + i, is64)
                              : i - N_EDGES;
        atomicAdd(&g_deg[d], 1);
    }
    if (i < N_NODES)
        g_batch[i] = idx_at(bav, i, g_b_is64);
}

__global__ void k_scan1() {
    __shared__ int sh[SCAN_BLK];
    int t = threadIdx.x;
    int i = blockIdx.x * SCAN_BLK + t;
    int v = (i < N_NODES) ? g_deg[i] : 0;
    sh[t] = v;
    __syncthreads();
#pragma unroll
    for (int off = 1; off < SCAN_BLK; off <<= 1) {
        int tmp = (t >= off) ? sh[t - off] : 0;
        __syncthreads();
        sh[t] += tmp;
        __syncthreads();
    }
    if (i < N_NODES) g_incl[i] = sh[t];
    if (t == SCAN_BLK - 1) g_bsum[blockIdx.x] = sh[t];
}

__global__ void k_scan3() {
    __shared__ int s_boff;
    if (threadIdx.x < 32) {
        int sb = blockIdx.x >> 2;    // scan1 block index (1024/256)
        int acc = 0;
        for (int j = threadIdx.x; j < sb; j += 32) acc += g_bsum[j];
#pragma unroll
        for (int off = 16; off >= 1; off >>= 1)
            acc += __shfl_xor_sync(0xffffffffu, acc, off);
        if (threadIdx.x == 0) s_boff = acc;
    }
    __syncthreads();
    int i = blockIdx.x * blockDim.x + threadIdx.x;
    if (i >= N_NODES) return;
    int rs = g_incl[i] - g_deg[i] + s_boff;
    g_rowstart[i] = rs;
    g_cursor[i]   = rs;
}

__global__ void k_scatter(const int* __restrict__ eiv) {
    int i = blockIdx.x * blockDim.x + threadIdx.x;
    if (i >= E_TOT) return;
    int s, d;
    if (i < N_EDGES) {
        int is64 = g_ei_is64;
        s = idx_at(eiv, i, is64);
        d = idx_at(eiv, N_EDGES + i, is64);
    } else {
        s = i - N_EDGES;
        d = s;
    }
    int p = atomicAdd(&g_cursor[d], 1);
    g_csr_src[p] = s;
}

// ---- layer 1: warp per dst node; direct single pass, no smem ----
__global__ void __launch_bounds__(256) k_l1(const float* __restrict__ x) {
    int w = (blockIdx.x * blockDim.x + threadIdx.x) >> 5;
    if (w >= N_NODES) return;
    int lane = threadIdx.x & 31;
    int eo = lane >> 3, h = lane & 7;
    int start = g_rowstart[w], end = g_rowstart[w + 1];
    float cs = g_s1[h];
    float cd = g_d1[h] * x[w];

    float den = 0.f, num = 0.f;
    for (int j = start + eo; j < end; j += 4) {
        float xs = x[__ldg(&g_csr_src[j])];
        float wj = __expf(fminf(lrelu(fmaf(xs, cs, cd)), 60.f));
        den += wj;
        num += wj * xs;
    }
#pragma unroll
    for (int off = 8; off <= 16; off <<= 1) {
        den += __shfl_xor_sync(0xffffffffu, den, off);
        num += __shfl_xor_sync(0xffffffffu, num, off);
    }
    if (lane < 8) g_t1[w * 8 + h] = num / den;
}

// ---- GEMM2 + fused elu input + fused att2 epilogue; h2 stored bf16 ----
__global__ void __launch_bounds__(128) k_gemm2(const float* __restrict__ W1,
                                               const float* __restrict__ b1,
                                               const float* __restrict__ W2,
                                               const float* __restrict__ att_src2,
                                               const float* __restrict__ att_dst2) {
    __shared__ float s_in[16][64];
    int t = threadIdx.x;
    int n0 = blockIdx.x * 16;
    for (int e = t; e < 1024; e += 128) {
        int nn = e >> 6, j = e & 63;
        float v = fmaf(g_t1[(n0 + nn) * 8 + (j >> 3)], W1[j], b1[j]);
        s_in[nn][j] = v > 0.f ? v : (__expf(v) - 1.f);
    }
    __syncthreads();
    int lane = t & 31;
    int ng = t >> 5;
    int c = lane * 4;
    int h = lane >> 2;
    unsigned long long acc01[4], acc23[4];
#pragma unroll
    for (int i = 0; i < 4; i++) { acc01[i] = 0ull; acc23[i] = 0ull; }
    const float* w2p = &W2[c];
#pragma unroll 4
    for (int k = 0; k < 64; k++) {
        float4 wv = *reinterpret_cast<const float4*>(w2p + k * 128);
        unsigned long long s01 = pack2(s_in[ng * 4 + 0][k], s_in[ng * 4 + 1][k]);
        unsigned long long s23 = pack2(s_in[ng * 4 + 2][k], s_in[ng * 4 + 3][k]);
        unsigned long long w0 = pack2(wv.x, wv.x);
        unsigned long long w1 = pack2(wv.y, wv.y);
        unsigned long long w2 = pack2(wv.z, wv.z);
        unsigned long long w3 = pack2(wv.w, wv.w);
        ffma2(acc01[0], w0, s01); ffma2(acc23[0], w0, s23);
        ffma2(acc01[1], w1, s01); ffma2(acc23[1], w1, s23);
        ffma2(acc01[2], w2, s01); ffma2(acc23[2], w2, s23);
        ffma2(acc01[3], w3, s01); ffma2(acc23[3], w3, s23);
    }
    float4 av = *reinterpret_cast<const float4*>(&att_src2[c]);
    float4 dv = *reinterpret_cast<const float4*>(&att_dst2[c]);
    float4 row[4];
    {
        float lo[4], hi[4];
#pragma unroll
        for (int i = 0; i < 4; i++) unpack2(acc01[i], lo[i], hi[i]);
        row[0] = make_float4(lo[0], lo[1], lo[2], lo[3]);
        row[1] = make_float4(hi[0], hi[1], hi[2], hi[3]);
#pragma unroll
        for (int i = 0; i < 4; i++) unpack2(acc23[i], lo[i], hi[i]);
        row[2] = make_float4(lo[0], lo[1], lo[2], lo[3]);
        row[3] = make_float4(hi[0], hi[1], hi[2], hi[3]);
    }
    int nb = n0 + ng * 4;
#pragma unroll
    for (int r = 0; r < 4; r++) {
        __nv_bfloat162 b0 = __float22bfloat162_rn(make_float2(row[r].x, row[r].y));
        __nv_bfloat162 b1v = __float22bfloat162_rn(make_float2(row[r].z, row[r].w));
        uint2 packed;
        packed.x = *reinterpret_cast<unsigned*>(&b0);
        packed.y = *reinterpret_cast<unsigned*>(&b1v);
        *reinterpret_cast<uint2*>(&g_h2b[(nb + r) * 64 + lane * 2]) = packed;
        float pa = row[r].x * av.x + row[r].y * av.y + row[r].z * av.z + row[r].w * av.w;
        float pd = row[r].x * dv.x + row[r].y * dv.y + row[r].z * dv.z + row[r].w * dv.w;
        pa += __shfl_xor_sync(0xffffffffu, pa, 1);
        pd += __shfl_xor_sync(0xffffffffu, pd, 1);
        pa += __shfl_xor_sync(0xffffffffu, pa, 2);
        pd += __shfl_xor_sync(0xffffffffu, pd, 2);
        if ((lane & 3) == 0) {
            g_as2[(nb + r) * 8 + h] = pa;
            g_ad2[(nb + r) * 8 + h] = pd;
        }
    }
}

// ---- layer 2: SINGLE PASS, zero smem; warp = 1 dst node; 8-edge unroll ----
__global__ void __launch_bounds__(256) k_l2() {
    int d = (blockIdx.x * blockDim.x + threadIdx.x) >> 5;
    if (d >= N_NODES) return;
    int lane = threadIdx.x & 31;
    int start = g_rowstart[d];
    int deg = g_rowstart[d + 1] - start;
    int sub = lane >> 4;       // which edge of the pair
    int q   = lane & 15;       // channel chunk: channels q*8 .. q*8+7
    int h4  = q >> 1;          // head owning this chunk
    float ad4 = g_ad2[d * 8 + h4];
    const int* srcp = &g_csr_src[start];

    float acc[8];
#pragma unroll
    for (int r = 0; r < 8; r++) acc[r] = 0.f;
    float wsum = 0.f;

    int k = 0;
    // 8 edges per iteration: 4 independent uint4 loads per lane in flight
    for (; k + 8 <= deg; k += 8) {
        int s0 = __ldg(&srcp[k + sub]);
        int s1 = __ldg(&srcp[k + 2 + sub]);
        int s2 = __ldg(&srcp[k + 4 + sub]);
        int s3 = __ldg(&srcp[k + 6 + sub]);
        uint4 v0 = *reinterpret_cast<const uint4*>(&g_h2b[s0 * 64 + q * 4]);
        uint4 v1 = *reinterpret_cast<const uint4*>(&g_h2b[s1 * 64 + q * 4]);
        uint4 v2 = *reinterpret_cast<const uint4*>(&g_h2b[s2 * 64 + q * 4]);
        uint4 v3 = *reinterpret_cast<const uint4*>(&g_h2b[s3 * 64 + q * 4]);
        float w0 = __expf(fminf(lrelu(g_as2[s0 * 8 + h4] + ad4), 60.f));
        float w1 = __expf(fminf(lrelu(g_as2[s1 * 8 + h4] + ad4), 60.f));
        float w2 = __expf(fminf(lrelu(g_as2[s2 * 8 + h4] + ad4), 60.f));
        float w3 = __expf(fminf(lrelu(g_as2[s3 * 8 + h4] + ad4), 60.f));
        wsum += (w0 + w1) + (w2 + w3);
        acc8(v0, w0, acc);
        acc8(v1, w1, acc);
        acc8(v2, w2, acc);
        acc8(v3, w3, acc);
    }
    for (; k + 4 <= deg; k += 4) {
        int s0 = __ldg(&srcp[k + sub]);
        int s1 = __ldg(&srcp[k + 2 + sub]);
        uint4 v0 = *reinterpret_cast<const uint4*>(&g_h2b[s0 * 64 + q * 4]);
        uint4 v1 = *reinterpret_cast<const uint4*>(&g_h2b[s1 * 64 + q * 4]);
        float w0 = __expf(fminf(lrelu(g_as2[s0 * 8 + h4] + ad4), 60.f));
        float w1 = __expf(fminf(lrelu(g_as2[s1 * 8 + h4] + ad4), 60.f));
        wsum += w0 + w1;
        acc8(v0, w0, acc);
        acc8(v1, w1, acc);
    }
    for (; k < deg; k += 2) {
        int idx = k + sub;
        bool valid = idx < deg;
        int s0 = __ldg(&srcp[valid ? idx : 0]);
        float w0 = valid
            ? __expf(fminf(lrelu(g_as2[s0 * 8 + h4] + ad4), 60.f)) : 0.f;
        uint4 v0 = *reinterpret_cast<const uint4*>(&g_h2b[s0 * 64 + q * 4]);
        wsum += w0;
        acc8(v0, w0, acc);
    }

    // merge the two edge-halves (lane ^ 16)
    wsum += __shfl_xor_sync(0xffffffffu, wsum, 16);
#pragma unroll
    for (int r = 0; r < 8; r++)
        acc[r] += __shfl_xor_sync(0xffffffffu, acc[r], 16);
    // normalize (per-head wsum) + head-mean factor
    float inv = 0.125f / wsum;
#pragma unroll
    for (int r = 0; r < 8; r++) acc[r] *= inv;
    // head reduce over q-pairs
#pragma unroll
    for (int off = 2; off <= 8; off <<= 1) {
#pragma unroll
        for (int r = 0; r < 8; r++)
            acc[r] += __shfl_xor_sync(0xffffffffu, acc[r], off);
    }
    if (lane < 2) {
        float4* dst = reinterpret_cast<float4*>(&g_pool[d * 16 + lane * 8]);
        dst[0] = make_float4(acc[0], acc[1], acc[2], acc[3]);
        dst[1] = make_float4(acc[4], acc[5], acc[6], acc[7]);
    }
}

// one block per graph: sum contiguous node range of g_pool, FC,
// then re-zero g_deg for the next launch.
__global__ void __launch_bounds__(256) k_final(const float* __restrict__ b2,
                                               const float* __restrict__ Wfc,
                                               const float* __restrict__ bfc,
                                               float* __restrict__ out) {
    __shared__ float s_part[8][16];
    __shared__ float s_pool[16];
    int g = blockIdx.x;
    int t = threadIdx.x;
    int lo = 0, hi = N_NODES;
    while (lo < hi) {
        int mid = (lo + hi) >> 1;
        if (g_batch[mid] < g) lo = mid + 1; else hi = mid;
    }
    int lb = lo;
    lo = 0; hi = N_NODES;
    while (lo < hi) {
        int mid = (lo + hi) >> 1;
        if (g_batch[mid] < g + 1) lo = mid + 1; else hi = mid;
    }
    int ub = lo;
    int c = t & 15;
    float acc = 0.f;
    for (int n = lb + (t >> 4); n < ub; n += 16)
        acc += g_pool[n * 16 + c];
    acc += __shfl_xor_sync(0xffffffffu, acc, 16);
    int wid = t >> 5, lane = t & 31;
    if (lane < 16) s_part[wid][lane] = acc;
    __syncthreads();
    if (t < 16) {
        float v = 0.f;
#pragma unroll
        for (int wds = 0; wds < 8; wds++) v += s_part[wds][t];
        float cnt = (float)(ub - lb);
        s_pool[t] = v / fmaxf(cnt, 1.f) + b2[t];
    }
    __syncthreads();
    if (t < 4) {
        float r = bfc[t];
#pragma unroll
        for (int cc = 0; cc < 16; cc++) r += s_pool[cc] * Wfc[cc * 4 + t];
        out[g * 4 + t] = r;
    }
    // re-zero deg for next launch (first launch covered by zero-init)
    for (int i = blockIdx.x * blockDim.x + t; i < N_NODES;
         i += gridDim.x * blockDim.x)
        g_deg[i] = 0;
}

// ---------------- launch ----------------
extern "C" void kernel_launch(void* const* d_in, const int* in_sizes, int n_in,
                              void* d_out, int out_size) {
    const float* x        = (const float*)d_in[0];
    const float* W1       = (const float*)d_in[1];
    const float* att_src1 = (const float*)d_in[2];
    const float* att_dst1 = (const float*)d_in[3];
    const float* b1       = (const float*)d_in[4];
    const float* W2       = (const float*)d_in[5];
    const float* att_src2 = (const float*)d_in[6];
    const float* att_dst2 = (const float*)d_in[7];
    const float* b2       = (const float*)d_in[8];
    const float* Wfc      = (const float*)d_in[9];
    const float* bfc      = (const float*)d_in[10];
    const int*   ei       = (const int*)d_in[11];
    const int*   batch    = (const int*)d_in[12];
    float* out = (float*)d_out;

    const int T = 256;
    int nb_nodes = (N_NODES + T - 1) / T;     // 391
    k_misc<<<1, 64>>>(ei, batch, W1, att_src1, att_dst1);
    k_hist<<<(E_TOT + T - 1) / T, T>>>(ei, batch);
    k_scan1<<<N_SBLK, SCAN_BLK>>>();
    k_scan3<<<nb_nodes, T>>>();
    k_scatter<<<(E_TOT + T - 1) / T, T>>>(ei);

    k_l1<<<(N_NODES * 32 + T - 1) / T, T>>>(x);
    k_gemm2<<<N_NODES / 16, 128>>>(W1, b1, W2, att_src2, att_dst2);
    k_l2<<<(N_NODES * 32 + T - 1) / T, T>>>();
    k_final<<<N_GRAPHS, 256>>>(b2, Wfc, bfc, out);
}